// round 6
// baseline (speedup 1.0000x reference)
#include <cuda_runtime.h>
#include <math.h>

#define OUT_F 512
#define IN_F  1024
#define BATCH 256
#define NSPLIT 16   // i-splits (64 inputs each, processed as 2×32 sub-slices)
#define JTILE  32   // output nodes per block

// Scratch (device globals — no allocation allowed anywhere)
__device__ float g_A[OUT_F * IN_F];              // additive mask: 0 (edge) / +4 (min-node masked) / -4 (max-node masked)
__device__ float g_P[NSPLIT * OUT_F * BATCH];    // partial reductions [s][j][b]

// ---------------------------------------------------------------------------
// Kernel 1: hard gumbel-softmax argmax -> additive mask
// ---------------------------------------------------------------------------
__global__ __launch_bounds__(256) void build_mask_kernel(
    const float* __restrict__ etc, const float* __restrict__ noise)
{
    int e = blockIdx.x * blockDim.x + threadIdx.x;   // e = j*IN_F + i
    if (e >= OUT_F * IN_F) return;
    const float eps = 1e-10f;
    float u0 = noise[2 * e + 0];
    float u1 = noise[2 * e + 1];
    float c0 = etc[2 * e + 0];
    float c1 = etc[2 * e + 1];
    float g0 = -logf(-logf(u0 + eps) + eps);
    float g1 = -logf(-logf(u1 + eps) + eps);
    // jnp.argmax ties break to index 0 (edge), so no_edge iff strictly greater
    bool no_edge = (c1 + g1) > (c0 + g0);
    int j = e >> 10;                                  // IN_F = 1024
    float off = (j & 1) ? -4.0f : 4.0f;
    g_A[e] = no_edge ? off : 0.0f;
}

// ---------------------------------------------------------------------------
// Kernel 2: masked min/max partial reduction.
// Block: 256 threads = all 256 batch rows. blockIdx.x = i-split (64 inputs,
// processed as two 32-input sub-slices), blockIdx.y = j-tile (32 nodes).
// Inner loop per element: 1 FADD (fma pipe) + 1 FMNMX (alu pipe).
// ---------------------------------------------------------------------------
__global__ __launch_bounds__(256) void reduce_kernel(const float* __restrict__ x)
{
    __shared__ float  xs[32][257];      // x transposed [i][b], padded (conflict-free)
    __shared__ float4 as4[JTILE][8];    // A[j][sub-slice of 32] as float4s

    const int s  = blockIdx.x;          // 0..NSPLIT-1
    const int jt = blockIdx.y;          // 0..15
    const int j0 = jt * JTILE;
    const int t  = threadIdx.x;         // = batch index b
    const int li = t & 31;
    const int lw = t >> 5;

    // Per-thread running accumulators across both sub-slices.
    // Registers: 16 j-pairs × 2 chains × (min,max interleaved) = 32 accs + 32 xr.
    float accm[JTILE / 2][2];           // min-nodes (even j)
    float accM[JTILE / 2][2];           // max-nodes (odd j)
    #pragma unroll
    for (int p = 0; p < JTILE / 2; p++) {
        accm[p][0] = accm[p][1] = 4.0f;
        accM[p][0] = accM[p][1] = -4.0f;
    }

    #pragma unroll 1
    for (int half = 0; half < 2; half++) {
        const int i0 = s * 64 + half * 32;

        if (half) __syncthreads();      // protect smem reuse from previous pass

        // Stage x sub-slice (each warp reads 32 consecutive floats per b: coalesced)
        #pragma unroll
        for (int k = 0; k < 32; k++) {
            int b = lw + k * 8;
            xs[li][b] = x[b * IN_F + i0 + li];
        }
        // Stage A tile (coalesced)
        #pragma unroll
        for (int k = 0; k < 4; k++) {
            int j = lw + k * 8;
            reinterpret_cast<float*>(&as4[j][0])[li] = g_A[(j0 + j) * IN_F + i0 + li];
        }
        __syncthreads();

        // Cache this thread's 32 x values in registers (reused across all 32 j)
        float xr[32];
        #pragma unroll
        for (int i = 0; i < 32; i++) xr[i] = xs[i][t];

        // (min-node, max-node) pairs: jj even -> global j even -> t-norm (min)
        #pragma unroll 1
        for (int jj = 0; jj < JTILE; jj += 2) {
            float m0 = accm[jj >> 1][0], m1 = accm[jj >> 1][1];
            float M0 = accM[jj >> 1][0], M1 = accM[jj >> 1][1];
            #pragma unroll
            for (int q = 0; q < 8; q++) {
                float4 a0 = as4[jj][q];       // warp-uniform LDS -> broadcast
                float4 a1 = as4[jj + 1][q];
                m0 = fminf(m0, xr[4 * q + 0] + a0.x);
                m1 = fminf(m1, xr[4 * q + 1] + a0.y);
                m0 = fminf(m0, xr[4 * q + 2] + a0.z);
                m1 = fminf(m1, xr[4 * q + 3] + a0.w);
                M0 = fmaxf(M0, xr[4 * q + 0] + a1.x);
                M1 = fmaxf(M1, xr[4 * q + 1] + a1.y);
                M0 = fmaxf(M0, xr[4 * q + 2] + a1.z);
                M1 = fmaxf(M1, xr[4 * q + 3] + a1.w);
            }
            accm[jj >> 1][0] = m0; accm[jj >> 1][1] = m1;
            accM[jj >> 1][0] = M0; accM[jj >> 1][1] = M1;
        }
    }

    // Emit partials
    #pragma unroll
    for (int jj = 0; jj < JTILE; jj += 2) {
        g_P[(s * OUT_F + j0 + jj) * BATCH + t]     = fminf(accm[jj >> 1][0], accm[jj >> 1][1]);
        g_P[(s * OUT_F + j0 + jj + 1) * BATCH + t] = fmaxf(accM[jj >> 1][0], accM[jj >> 1][1]);
    }
}

// ---------------------------------------------------------------------------
// Kernel 3: combine the NSPLIT partials, apply the exact no-edge identity clamp.
// ---------------------------------------------------------------------------
__global__ __launch_bounds__(256) void combine_kernel(float* __restrict__ out)
{
    int tid = blockIdx.x * blockDim.x + threadIdx.x;  // 131072 threads
    int b = tid & (BATCH - 1);
    int j = tid >> 8;
    if ((j & 1) == 0) {
        float acc = 4.0f;
        #pragma unroll
        for (int s = 0; s < NSPLIT; s++)
            acc = fminf(acc, g_P[(s * OUT_F + j) * BATCH + b]);
        out[b * OUT_F + j] = fminf(acc, 2.0f);   // exact identity offset if all masked
    } else {
        float acc = -4.0f;
        #pragma unroll
        for (int s = 0; s < NSPLIT; s++)
            acc = fmaxf(acc, g_P[(s * OUT_F + j) * BATCH + b]);
        out[b * OUT_F + j] = fmaxf(acc, -1.0f);
    }
}

// ---------------------------------------------------------------------------
extern "C" void kernel_launch(void* const* d_in, const int* in_sizes, int n_in,
                              void* d_out, int out_size)
{
    const float* x     = (const float*)d_in[0];   // [256, 1024]
    const float* etc   = (const float*)d_in[1];   // [512, 1024, 2]
    const float* noise = (const float*)d_in[2];   // [512, 1024, 2]
    float* out = (float*)d_out;                   // [256, 512]

    build_mask_kernel<<<(OUT_F * IN_F + 255) / 256, 256>>>(etc, noise);
    reduce_kernel<<<dim3(NSPLIT, OUT_F / JTILE), 256>>>(x);
    combine_kernel<<<(BATCH * OUT_F + 255) / 256, 256>>>(out);
}

// round 8
// speedup vs baseline: 1.5567x; 1.5567x over previous
#include <cuda_runtime.h>
#include <cuda_fp16.h>
#include <math.h>

#define OUT_F 512
#define IN_F  1024
#define BATCH 256
#define NPAIR 128          // batch pairs (2 rows per half2 lane)
#define NSPLIT 32          // i-splits of 32 inputs each
#define JTILE  32          // output nodes per reduce block

// Scratch (device globals — no allocation allowed anywhere)
__device__ __half2 g_Ah2[OUT_F * IN_F];          // additive mask, duplicated into both halves: (0,0) / (+4,+4) / (-4,-4)
__device__ __half2 g_Xt[IN_F * NPAIR];           // x transposed+packed: g_Xt[i*128+p] = (x[2p][i], x[2p+1][i])
__device__ __half2 g_P[NSPLIT * OUT_F * NPAIR];  // partial reductions [s][j][p]

static __device__ __forceinline__ __half2 u2h2(unsigned v) {
    return *reinterpret_cast<__half2*>(&v);
}

// ---------------------------------------------------------------------------
// Kernel 1 (fused): blocks [0,2048): hard gumbel argmax -> fp16 additive mask.
//                   blocks [2048,2176): transpose/pack x into half2 [i][pair].
// Mask decision math is bit-identical to the previously verified fp32 path.
// ---------------------------------------------------------------------------
__global__ __launch_bounds__(256) void prep_kernel(
    const float* __restrict__ etc, const float* __restrict__ noise,
    const float* __restrict__ x)
{
    const int bid = blockIdx.x;
    const int tid = threadIdx.x;
    __shared__ float ts[64][33];

    if (bid < 2048) {
        int e = bid * 256 + tid;                      // e = j*IN_F + i
        const float eps = 1e-10f;
        float u0 = noise[2 * e + 0];
        float u1 = noise[2 * e + 1];
        float c0 = etc[2 * e + 0];
        float c1 = etc[2 * e + 1];
        float g0 = -logf(-logf(u0 + eps) + eps);
        float g1 = -logf(-logf(u1 + eps) + eps);
        // jnp.argmax ties break to index 0 (edge): no_edge iff strictly greater
        bool no_edge = (c1 + g1) > (c0 + g0);
        int j = e >> 10;                              // IN_F = 1024
        float off = (j & 1) ? -4.0f : 4.0f;
        float a = no_edge ? off : 0.0f;
        g_Ah2[e] = __half2half2(__float2half_rn(a));  // 0 / ±4: exact in fp16
    } else {
        // transpose tile: 32 i-cols x 64 b-rows
        int b2 = bid - 2048;                          // 0..127
        int it = b2 & 31, bt = b2 >> 5;
        int i0 = it * 32, b0 = bt * 64;
        int col = tid & 31, rw = tid >> 5;
        #pragma unroll
        for (int k = 0; k < 8; k++)
            ts[rw + k * 8][col] = x[(b0 + rw + k * 8) * IN_F + i0 + col];  // coalesced
        __syncthreads();
        #pragma unroll
        for (int k = 0; k < 4; k++) {
            int idx = tid + k * 256;                  // 0..1023
            int il = idx >> 5, pl = idx & 31;
            float lo = ts[2 * pl + 0][il];
            float hi = ts[2 * pl + 1][il];
            g_Xt[(i0 + il) * NPAIR + (b0 >> 1) + pl] = __floats2half2_rn(lo, hi);  // coalesced
        }
    }
}

// ---------------------------------------------------------------------------
// Kernel 2: packed masked min/max partial reduction.
// Block: 128 threads = all 128 batch pairs. blockIdx = (i-split of 32, j-tile
// of 32 nodes). Inner loop per 2 elements: 1 HADD2 (fma pipe) + 1 HMNMX2
// (alu pipe) -> 1 issue slot per element.
// ---------------------------------------------------------------------------
__global__ __launch_bounds__(128) void reduce_kernel()
{
    __shared__ __half2 As[JTILE][32];    // A tile [j][i], rows = 128B

    const int s  = blockIdx.x;           // 0..31
    const int jt = blockIdx.y;           // 0..15
    const int i0 = s * 32;
    const int j0 = jt * JTILE;
    const int p  = threadIdx.x;          // batch-pair index

    // Stage A tile (1024 half2; 8 per thread, coalesced 128B rows)
    #pragma unroll
    for (int k = 0; k < 8; k++) {
        int idx = p + k * 128;
        int jl = idx >> 5, il = idx & 31;
        As[jl][il] = g_Ah2[(j0 + jl) * IN_F + i0 + il];
    }
    // Cache this pair's 32 x values in registers (reused across all 32 j)
    __half2 xr[32];
    #pragma unroll
    for (int k = 0; k < 32; k++)
        xr[k] = g_Xt[(i0 + k) * NPAIR + p];          // 128B coalesced per warp
    __syncthreads();

    const __half2 PI = __float2half2_rn(4.0f);       // min identity (> any unmasked)
    const __half2 NI = __float2half2_rn(-4.0f);      // max identity

    // (min-node, max-node) pairs; jj even -> global j even -> t-norm (min)
    #pragma unroll 1
    for (int jj = 0; jj < JTILE; jj += 2) {
        __half2 m0 = PI, m1 = PI;                    // 4 chains for ILP
        __half2 M0 = NI, M1 = NI;
        const uint4* a0p = reinterpret_cast<const uint4*>(&As[jj][0]);
        const uint4* a1p = reinterpret_cast<const uint4*>(&As[jj + 1][0]);
        #pragma unroll
        for (int q = 0; q < 8; q++) {
            uint4 a0 = a0p[q];                       // LDS.128 uniform -> broadcast
            uint4 a1 = a1p[q];
            m0 = __hmin2(m0, __hadd2(xr[4 * q + 0], u2h2(a0.x)));
            m1 = __hmin2(m1, __hadd2(xr[4 * q + 1], u2h2(a0.y)));
            m0 = __hmin2(m0, __hadd2(xr[4 * q + 2], u2h2(a0.z)));
            m1 = __hmin2(m1, __hadd2(xr[4 * q + 3], u2h2(a0.w)));
            M0 = __hmax2(M0, __hadd2(xr[4 * q + 0], u2h2(a1.x)));
            M1 = __hmax2(M1, __hadd2(xr[4 * q + 1], u2h2(a1.y)));
            M0 = __hmax2(M0, __hadd2(xr[4 * q + 2], u2h2(a1.z)));
            M1 = __hmax2(M1, __hadd2(xr[4 * q + 3], u2h2(a1.w)));
        }
        g_P[(s * OUT_F + j0 + jj + 0) * NPAIR + p] = __hmin2(m0, m1);  // coalesced
        g_P[(s * OUT_F + j0 + jj + 1) * NPAIR + p] = __hmax2(M0, M1);
    }
}

// ---------------------------------------------------------------------------
// Kernel 3: combine the NSPLIT partials (packed), unpack, exact identity clamp.
// ---------------------------------------------------------------------------
__global__ __launch_bounds__(256) void combine_kernel(float* __restrict__ out)
{
    int g = blockIdx.x * blockDim.x + threadIdx.x;   // 65536 threads
    int j = g >> 7;                                  // 0..511 (warp-uniform)
    int p = g & (NPAIR - 1);
    if ((j & 1) == 0) {
        __half2 acc = __float2half2_rn(4.0f);
        #pragma unroll
        for (int s = 0; s < NSPLIT; s++)
            acc = __hmin2(acc, g_P[(s * OUT_F + j) * NPAIR + p]);
        float lo = fminf(__low2float(acc),  2.0f);   // exact identity if all masked
        float hi = fminf(__high2float(acc), 2.0f);
        out[(2 * p + 0) * OUT_F + j] = lo;
        out[(2 * p + 1) * OUT_F + j] = hi;
    } else {
        __half2 acc = __float2half2_rn(-4.0f);
        #pragma unroll
        for (int s = 0; s < NSPLIT; s++)
            acc = __hmax2(acc, g_P[(s * OUT_F + j) * NPAIR + p]);
        float lo = fmaxf(__low2float(acc),  -1.0f);
        float hi = fmaxf(__high2float(acc), -1.0f);
        out[(2 * p + 0) * OUT_F + j] = lo;
        out[(2 * p + 1) * OUT_F + j] = hi;
    }
}

// ---------------------------------------------------------------------------
extern "C" void kernel_launch(void* const* d_in, const int* in_sizes, int n_in,
                              void* d_out, int out_size)
{
    const float* x     = (const float*)d_in[0];   // [256, 1024]
    const float* etc   = (const float*)d_in[1];   // [512, 1024, 2]
    const float* noise = (const float*)d_in[2];   // [512, 1024, 2]
    float* out = (float*)d_out;                   // [256, 512]

    prep_kernel<<<2048 + 128, 256>>>(etc, noise, x);
    reduce_kernel<<<dim3(NSPLIT, OUT_F / JTILE), 128>>>();
    combine_kernel<<<(OUT_F * NPAIR + 255) / 256, 256>>>(out);
}